// round 2
// baseline (speedup 1.0000x reference)
#include <cuda_runtime.h>

#define NB   8192
#define NOPT 16
#define DIM  768
#define F4_PER_ROW (DIM / 4)   // 192
#define MARGIN 0.3f

// Scratch: per-sample partial results (deterministic two-pass reduction).
__device__ float g_loss[NB];
__device__ int   g_cnt[NB];

// pair index for (i<=j) in triangular enumeration; folds to a constant under unroll
__device__ __forceinline__ constexpr int pidx(int i, int j) {
    return i * NOPT - (i * (i - 1)) / 2 + (j - i);
}

template <int LO, int HI>
__device__ __forceinline__ void accum_pairs(float (&acc)[HI - LO], const float4 (&x)[NOPT]) {
#pragma unroll
    for (int i = 0; i < NOPT; ++i) {
#pragma unroll
        for (int j = i; j < NOPT; ++j) {
            const int p = pidx(i, j);
            if (p >= LO && p < HI) {
                float a = acc[p - LO];
                a = fmaf(x[i].x, x[j].x, a);
                a = fmaf(x[i].y, x[j].y, a);
                a = fmaf(x[i].z, x[j].z, a);
                a = fmaf(x[i].w, x[j].w, a);
                acc[p - LO] = a;
            }
        }
    }
}

template <int LO, int HI>
__device__ __forceinline__ void reduce_store(float (&acc)[HI - LO], float* G, int lane) {
#pragma unroll
    for (int i = 0; i < NOPT; ++i) {
#pragma unroll
        for (int j = i; j < NOPT; ++j) {
            const int p = pidx(i, j);
            if (p >= LO && p < HI) {
                float v = acc[p - LO];
                v += __shfl_xor_sync(0xFFFFFFFFu, v, 16);
                v += __shfl_xor_sync(0xFFFFFFFFu, v, 8);
                v += __shfl_xor_sync(0xFFFFFFFFu, v, 4);
                v += __shfl_xor_sync(0xFFFFFFFFu, v, 2);
                v += __shfl_xor_sync(0xFFFFFFFFu, v, 1);
                if (lane == 0) {
                    G[i * NOPT + j] = v;
                    G[j * NOPT + i] = v;
                }
            }
        }
    }
}

template <int LO, int HI>
__device__ __forceinline__ void sample_work(const float4* __restrict__ base,
                                            float* __restrict__ G, int lane) {
    float acc[HI - LO] = {};
    float4 x[NOPT];
    for (int k = 0; k < 6; ++k) {
        const float4* p0 = base + lane + 32 * k;
#pragma unroll
        for (int n = 0; n < NOPT; ++n) x[n] = p0[n * F4_PER_ROW];
        accum_pairs<LO, HI>(acc, x);
    }
    reduce_store<LO, HI>(acc, G, lane);
}

// 256 threads = 8 warps; warps 0-3 handle sample 2b, warps 4-7 handle 2b+1.
// Each warp owns 34 of the 136 unique Gram pairs (acc[34] keeps regs ~120 ->
// 4 warps/SMSP occupancy; wid%4 covers all 4 SMSPs).
__global__ void __launch_bounds__(256)
cf_main(const float* __restrict__ emb, const long long* __restrict__ labels) {
    const int tid  = threadIdx.x;
    const int half = tid >> 7;            // which sample within CTA
    const int ht   = tid & 127;           // thread index within sample group
    const int wis  = ht >> 5;             // warp-in-sample 0..3
    const int lane = tid & 31;
    const int b    = blockIdx.x * 2 + half;

    __shared__ float G[2][NOPT * NOPT];
    __shared__ float invn[2][NOPT];
    __shared__ int   lab[2][NOPT];

    if (ht < NOPT) lab[half][ht] = (int)labels[(size_t)b * NOPT + ht];

    const float4* base = reinterpret_cast<const float4*>(emb + (size_t)b * NOPT * DIM);

    switch (wis) {
        case 0: sample_work<0,   34 >(base, G[half], lane); break;
        case 1: sample_work<34,  68 >(base, G[half], lane); break;
        case 2: sample_work<68,  102>(base, G[half], lane); break;
        default: sample_work<102, 136>(base, G[half], lane); break;
    }
    __syncthreads();

    if (ht < NOPT) invn[half][ht] = rsqrtf(fmaxf(G[half][ht * NOPT + ht], 1e-24f));
    __syncthreads();

    if (ht < NOPT) {
        const int  n     = ht;
        const bool isPos = (lab[half][n] == 1);
        const bool isNeg = (lab[half][n] == 0);
        const unsigned posm = __ballot_sync(0x0000FFFFu, isPos) & 0xFFFFu;
        const unsigned negm = __ballot_sync(0x0000FFFFu, isNeg) & 0xFFFFu;
        const bool valid = (posm != 0u) && (negm != 0u);

        const float in_ = invn[half][n];
        float mx = -1e9f;   // NEG_INF sentinel, matches reference
#pragma unroll
        for (int m = 0; m < NOPT; ++m) {
            if (lab[half][m] == 0)
                mx = fmaxf(mx, G[half][n * NOPT + m] * in_ * invn[half][m]);
        }
        const float trip = fmaxf(mx + MARGIN, 0.0f);
        float contrib = (isPos && valid) ? trip : 0.0f;

        contrib += __shfl_xor_sync(0x0000FFFFu, contrib, 8);
        contrib += __shfl_xor_sync(0x0000FFFFu, contrib, 4);
        contrib += __shfl_xor_sync(0x0000FFFFu, contrib, 2);
        contrib += __shfl_xor_sync(0x0000FFFFu, contrib, 1);

        if (n == 0) {
            g_loss[b] = contrib;
            g_cnt[b]  = valid ? __popc(posm) : 0;
        }
    }
}

__global__ void __launch_bounds__(1024)
cf_final(float* __restrict__ out) {
    __shared__ float ssum[32];
    __shared__ int   scnt[32];
    const int tid  = threadIdx.x;
    const int lane = tid & 31;
    const int wid  = tid >> 5;

    float s = 0.0f;
    int   c = 0;
#pragma unroll
    for (int i = tid; i < NB; i += 1024) { s += g_loss[i]; c += g_cnt[i]; }

#pragma unroll
    for (int off = 16; off > 0; off >>= 1) {
        s += __shfl_xor_sync(0xFFFFFFFFu, s, off);
        c += __shfl_xor_sync(0xFFFFFFFFu, c, off);
    }
    if (lane == 0) { ssum[wid] = s; scnt[wid] = c; }
    __syncthreads();

    if (wid == 0) {
        float s2 = ssum[lane];
        int   c2 = scnt[lane];
#pragma unroll
        for (int off = 16; off > 0; off >>= 1) {
            s2 += __shfl_xor_sync(0xFFFFFFFFu, s2, off);
            c2 += __shfl_xor_sync(0xFFFFFFFFu, c2, off);
        }
        if (lane == 0) out[0] = s2 / (float)(c2 > 0 ? c2 : 1);
    }
}

extern "C" void kernel_launch(void* const* d_in, const int* in_sizes, int n_in,
                              void* d_out, int out_size) {
    const float*     emb    = (const float*)d_in[0];
    const long long* labels = (const long long*)d_in[1];
    float*           out    = (float*)d_out;

    cf_main<<<NB / 2, 256>>>(emb, labels);
    cf_final<<<1, 1024>>>(out);
}

// round 3
// speedup vs baseline: 1.0366x; 1.0366x over previous
#include <cuda_runtime.h>

#define NB   8192
#define NOPT 16
#define DIM  768
#define F4_PER_ROW (DIM / 4)   // 192 16-byte chunks per row
#define MARGIN 0.3f
#define NPAIR 136
#define STG_PITCH 33           // pad to 33 floats -> conflict-free STS and LDS

// Scratch: per-sample partial results (deterministic two-pass reduction).
__device__ float g_loss[NB];
__device__ int   g_cnt[NB];

// pair index for (i<=j) in triangular enumeration; folds to a constant under unroll
__device__ __forceinline__ constexpr int pidx(int i, int j) {
    return i * NOPT - (i * (i - 1)) / 2 + (j - i);
}

// Blackwell packed fp32x2 FMA: one instruction does 2 fp32 FMAs.
__device__ __forceinline__ void fma2(unsigned long long& acc,
                                     unsigned long long a,
                                     unsigned long long b) {
    asm("fma.rn.f32x2 %0, %1, %2, %0;" : "+l"(acc) : "l"(a), "l"(b));
}

template <int LO, int HI>
__device__ __forceinline__ void accum_pairs(unsigned long long (&acc)[HI - LO],
                                            const ulonglong2 (&x)[NOPT]) {
#pragma unroll
    for (int i = 0; i < NOPT; ++i) {
#pragma unroll
        for (int j = i; j < NOPT; ++j) {
            const int p = pidx(i, j);
            if (p >= LO && p < HI) {
                fma2(acc[p - LO], x[i].x, x[j].x);   // dims 0,1 of this 16B chunk
                fma2(acc[p - LO], x[i].y, x[j].y);   // dims 2,3
            }
        }
    }
}

// One warp: accumulate 68 pairs over the full 768 dims (lane-strided float4
// chunks), then combine packed halves and stage per-lane partials to smem.
template <int LO, int HI>
__device__ __forceinline__ void sample_work(const ulonglong2* __restrict__ base,
                                            float* __restrict__ stage, int lane) {
    unsigned long long acc[HI - LO] = {};
    ulonglong2 x[NOPT];
    for (int k = 0; k < 6; ++k) {
        const ulonglong2* p0 = base + lane + 32 * k;
#pragma unroll
        for (int n = 0; n < NOPT; ++n) x[n] = p0[n * F4_PER_ROW];
        accum_pairs<LO, HI>(acc, x);
    }
#pragma unroll
    for (int p = LO; p < HI; ++p) {
        const unsigned long long v = acc[p - LO];
        const float lo = __uint_as_float((unsigned)(v & 0xFFFFFFFFu));
        const float hi = __uint_as_float((unsigned)(v >> 32));
        stage[p * STG_PITCH + lane] = lo + hi;
    }
}

// 128 threads = 4 warps = 2 samples x 2 warps. Warp w%2 owns pair range,
// w/2 owns the sample. All 4 SMSPs covered per CTA.
__global__ void __launch_bounds__(128)
cf_main(const float* __restrict__ emb, const long long* __restrict__ labels) {
    const int tid  = threadIdx.x;
    const int half = tid >> 6;            // sample within CTA
    const int ht   = tid & 63;            // thread within sample group
    const int wis  = (tid >> 5) & 1;      // warp-in-sample
    const int lane = tid & 31;
    const int b    = blockIdx.x * 2 + half;

    __shared__ float stage[2][NPAIR * STG_PITCH];
    __shared__ float G[2][NOPT * NOPT];
    __shared__ float invn[2][NOPT];
    __shared__ int   lab[2][NOPT];

    if (ht < NOPT) lab[half][ht] = (int)labels[(size_t)b * NOPT + ht];

    const ulonglong2* base =
        reinterpret_cast<const ulonglong2*>(emb + (size_t)b * NOPT * DIM);

    if (wis == 0) sample_work<0, 68>(base, stage[half], lane);
    else          sample_work<68, 136>(base, stage[half], lane);
    __syncthreads();

    // Cross-lane reduction from smem: conflict-free (pitch 33), pair p handled
    // by thread ht, ht+64 within the sample's 64 threads.
    for (int p = ht; p < NPAIR; p += 64) {
        const float* row = stage[half] + p * STG_PITCH;
        float s = 0.0f;
#pragma unroll
        for (int t = 0; t < 32; ++t) s += row[t];
        // triangular p -> (i, j)
        int i = 0, rem = p;
        while (rem >= NOPT - i) { rem -= NOPT - i; ++i; }
        const int j = i + rem;
        G[half][i * NOPT + j] = s;
        G[half][j * NOPT + i] = s;
    }
    __syncthreads();

    if (ht < NOPT) invn[half][ht] = rsqrtf(fmaxf(G[half][ht * NOPT + ht], 1e-24f));
    __syncthreads();

    if (ht < NOPT) {
        const int  n     = ht;
        const bool isPos = (lab[half][n] == 1);
        const bool isNeg = (lab[half][n] == 0);
        const unsigned posm = __ballot_sync(0x0000FFFFu, isPos) & 0xFFFFu;
        const unsigned negm = __ballot_sync(0x0000FFFFu, isNeg) & 0xFFFFu;
        const bool valid = (posm != 0u) && (negm != 0u);

        const float in_ = invn[half][n];
        float mx = -1e9f;   // NEG_INF sentinel, matches reference
#pragma unroll
        for (int m = 0; m < NOPT; ++m) {
            if (lab[half][m] == 0)
                mx = fmaxf(mx, G[half][n * NOPT + m] * in_ * invn[half][m]);
        }
        const float trip = fmaxf(mx + MARGIN, 0.0f);
        float contrib = (isPos && valid) ? trip : 0.0f;

        contrib += __shfl_xor_sync(0x0000FFFFu, contrib, 8);
        contrib += __shfl_xor_sync(0x0000FFFFu, contrib, 4);
        contrib += __shfl_xor_sync(0x0000FFFFu, contrib, 2);
        contrib += __shfl_xor_sync(0x0000FFFFu, contrib, 1);

        if (n == 0) {
            g_loss[b] = contrib;
            g_cnt[b]  = valid ? __popc(posm) : 0;
        }
    }
}

__global__ void __launch_bounds__(1024)
cf_final(float* __restrict__ out) {
    __shared__ float ssum[32];
    __shared__ int   scnt[32];
    const int tid  = threadIdx.x;
    const int lane = tid & 31;
    const int wid  = tid >> 5;

    float s = 0.0f;
    int   c = 0;
#pragma unroll
    for (int i = tid; i < NB; i += 1024) { s += g_loss[i]; c += g_cnt[i]; }

#pragma unroll
    for (int off = 16; off > 0; off >>= 1) {
        s += __shfl_xor_sync(0xFFFFFFFFu, s, off);
        c += __shfl_xor_sync(0xFFFFFFFFu, c, off);
    }
    if (lane == 0) { ssum[wid] = s; scnt[wid] = c; }
    __syncthreads();

    if (wid == 0) {
        float s2 = ssum[lane];
        int   c2 = scnt[lane];
#pragma unroll
        for (int off = 16; off > 0; off >>= 1) {
            s2 += __shfl_xor_sync(0xFFFFFFFFu, s2, off);
            c2 += __shfl_xor_sync(0xFFFFFFFFu, c2, off);
        }
        if (lane == 0) out[0] = s2 / (float)(c2 > 0 ? c2 : 1);
    }
}

extern "C" void kernel_launch(void* const* d_in, const int* in_sizes, int n_in,
                              void* d_out, int out_size) {
    const float*     emb    = (const float*)d_in[0];
    const long long* labels = (const long long*)d_in[1];
    float*           out    = (float*)d_out;

    cf_main<<<NB / 2, 128>>>(emb, labels);
    cf_final<<<1, 1024>>>(out);
}

// round 5
// speedup vs baseline: 1.1190x; 1.0794x over previous
#include <cuda_runtime.h>

#define NB   8192
#define NOPT 16
#define DIM  768
#define F4_PER_ROW (DIM / 4)   // 192
#define MARGIN 0.3f

// Scratch: per-sample partial results (deterministic two-pass reduction).
__device__ float g_loss[NB];
__device__ int   g_cnt[NB];

// pair index for (i<=j) in triangular enumeration; folds to a constant under unroll
__device__ __forceinline__ constexpr int pidx(int i, int j) {
    return i * NOPT - (i * (i - 1)) / 2 + (j - i);
}

template <int LO, int HI>
__device__ __forceinline__ void accum_pairs(float (&acc)[HI - LO], const float4 (&x)[NOPT]) {
#pragma unroll
    for (int i = 0; i < NOPT; ++i) {
#pragma unroll
        for (int j = i; j < NOPT; ++j) {
            const int p = pidx(i, j);
            if (p >= LO && p < HI) {
                float a = acc[p - LO];
                a = fmaf(x[i].x, x[j].x, a);
                a = fmaf(x[i].y, x[j].y, a);
                a = fmaf(x[i].z, x[j].z, a);
                a = fmaf(x[i].w, x[j].w, a);
                acc[p - LO] = a;
            }
        }
    }
}

template <int LO, int HI>
__device__ __forceinline__ void reduce_store(float (&acc)[HI - LO], float* G, int lane) {
#pragma unroll
    for (int i = 0; i < NOPT; ++i) {
#pragma unroll
        for (int j = i; j < NOPT; ++j) {
            const int p = pidx(i, j);
            if (p >= LO && p < HI) {
                float v = acc[p - LO];
                v += __shfl_xor_sync(0xFFFFFFFFu, v, 16);
                v += __shfl_xor_sync(0xFFFFFFFFu, v, 8);
                v += __shfl_xor_sync(0xFFFFFFFFu, v, 4);
                v += __shfl_xor_sync(0xFFFFFFFFu, v, 2);
                v += __shfl_xor_sync(0xFFFFFFFFu, v, 1);
                if (lane == 0) {
                    G[i * NOPT + j] = v;
                    G[j * NOPT + i] = v;
                }
            }
        }
    }
}

template <int LO, int HI>
__device__ __forceinline__ void sample_work(const float4* __restrict__ base,
                                            float* __restrict__ G, int lane) {
    float acc[HI - LO] = {};
    float4 x[NOPT];
    for (int k = 0; k < 6; ++k) {
        const float4* p0 = base + lane + 32 * k;
#pragma unroll
        for (int n = 0; n < NOPT; ++n) x[n] = p0[n * F4_PER_ROW];
        accum_pairs<LO, HI>(acc, x);
    }
    reduce_store<LO, HI>(acc, G, lane);
}

// 128 threads = 4 warps = 2 samples x 2 warps. Warp-in-block 0..3 covers all
// 4 SMSPs (wid%4) -- the R1 64-thread CTA left SMSP 2,3 idle.
__global__ void __launch_bounds__(128)
cf_main(const float* __restrict__ emb, const long long* __restrict__ labels) {
    const int tid  = threadIdx.x;
    const int half = tid >> 6;            // sample within CTA
    const int ht   = tid & 63;            // thread within sample group
    const int wis  = (tid >> 5) & 1;      // warp-in-sample 0..1
    const int lane = tid & 31;
    const int b    = blockIdx.x * 2 + half;

    __shared__ float G[2][NOPT * NOPT];
    __shared__ float invn[2][NOPT];
    __shared__ int   lab[2][NOPT];

    if (ht < NOPT) lab[half][ht] = (int)labels[(size_t)b * NOPT + ht];

    const float4* base = reinterpret_cast<const float4*>(emb + (size_t)b * NOPT * DIM);

    if (wis == 0) sample_work<0, 68>(base, G[half], lane);
    else          sample_work<68, 136>(base, G[half], lane);
    __syncthreads();

    if (ht < NOPT) invn[half][ht] = rsqrtf(fmaxf(G[half][ht * NOPT + ht], 1e-24f));
    __syncthreads();

    if (ht < NOPT) {
        const int  n     = ht;
        const bool isPos = (lab[half][n] == 1);
        const bool isNeg = (lab[half][n] == 0);
        const unsigned posm = __ballot_sync(0x0000FFFFu, isPos) & 0xFFFFu;
        const unsigned negm = __ballot_sync(0x0000FFFFu, isNeg) & 0xFFFFu;
        const bool valid = (posm != 0u) && (negm != 0u);

        const float in_ = invn[half][n];
        float mx = -1e9f;   // NEG_INF sentinel, matches reference
#pragma unroll
        for (int m = 0; m < NOPT; ++m) {
            if (lab[half][m] == 0)
                mx = fmaxf(mx, G[half][n * NOPT + m] * in_ * invn[half][m]);
        }
        const float trip = fmaxf(mx + MARGIN, 0.0f);
        float contrib = (isPos && valid) ? trip : 0.0f;

        contrib += __shfl_xor_sync(0x0000FFFFu, contrib, 8);
        contrib += __shfl_xor_sync(0x0000FFFFu, contrib, 4);
        contrib += __shfl_xor_sync(0x0000FFFFu, contrib, 2);
        contrib += __shfl_xor_sync(0x0000FFFFu, contrib, 1);

        if (n == 0) {
            g_loss[b] = contrib;
            g_cnt[b]  = valid ? __popc(posm) : 0;
        }
    }
}

__global__ void __launch_bounds__(1024)
cf_final(float* __restrict__ out) {
    __shared__ float ssum[32];
    __shared__ int   scnt[32];
    const int tid  = threadIdx.x;
    const int lane = tid & 31;
    const int wid  = tid >> 5;

    // 8192 elements / 1024 threads = 2 float4 / 2 int4 per thread.
    const float4* lf = reinterpret_cast<const float4*>(g_loss);
    const int4*   lc = reinterpret_cast<const int4*>(g_cnt);
    float s = 0.0f;
    int   c = 0;
#pragma unroll
    for (int r = 0; r < 2; ++r) {
        const float4 v = lf[tid + r * 1024];
        const int4   w = lc[tid + r * 1024];
        s += (v.x + v.y) + (v.z + v.w);
        c += (w.x + w.y) + (w.z + w.w);
    }

#pragma unroll
    for (int off = 16; off > 0; off >>= 1) {
        s += __shfl_xor_sync(0xFFFFFFFFu, s, off);
        c += __shfl_xor_sync(0xFFFFFFFFu, c, off);
    }
    if (lane == 0) { ssum[wid] = s; scnt[wid] = c; }
    __syncthreads();

    if (wid == 0) {
        float s2 = ssum[lane];
        int   c2 = scnt[lane];
#pragma unroll
        for (int off = 16; off > 0; off >>= 1) {
            s2 += __shfl_xor_sync(0xFFFFFFFFu, s2, off);
            c2 += __shfl_xor_sync(0xFFFFFFFFu, c2, off);
        }
        if (lane == 0) out[0] = s2 / (float)(c2 > 0 ? c2 : 1);
    }
}

// No-op: shifts launch indices so ncu's "-s 5" lands on cf_main (launch #5
// across two kernel_launch calls of 4 launches each).
__global__ void cf_nop() {}

extern "C" void kernel_launch(void* const* d_in, const int* in_sizes, int n_in,
                              void* d_out, int out_size) {
    const float*     emb    = (const float*)d_in[0];
    const long long* labels = (const long long*)d_in[1];
    float*           out    = (float*)d_out;

    cf_nop<<<1, 32>>>();
    cf_main<<<NB / 2, 128>>>(emb, labels);
    cf_final<<<1, 1024>>>(out);
    cf_nop<<<1, 32>>>();
}